// round 6
// baseline (speedup 1.0000x reference)
#include <cuda_runtime.h>

#define DEV_INLINE __device__ __forceinline__

constexpr int NN   = 1024;
constexpr int EE   = 65536;
constexpr int E2   = EE + NN;      // edges + self loops
constexpr int W1O  = 512;          // H*256
constexpr int C1   = 256;
constexpr int W2O  = 128;          // H*64
constexpr int C2   = 64;

// ---------------- scratch (device globals) -------------
__device__ float g_xp[2][NN * W1O];
__device__ float g_h1[NN * W1O];
__device__ float g_att[2 * 2 * NN * 2];   // [rel][als/ald][node*2+head]
__device__ int   g_cnt[2][NN];
__device__ int   g_off[2][NN + 1];
__device__ int   g_cur[2][NN];
__device__ int   g_srcs[2][E2];
__device__ float g_s[NN];

// =======================================================================
// FUSED launch: gemm1 (both relations) + attn1 logits (atomic epilogue)
//               + edge counting
// =======================================================================
constexpr int G1_GEMM_BLOCKS  = (W1O / 64) * (NN / 128) * 2;   // 128
constexpr int G1_COUNT_BLOCKS = EE / 4 / 256;                  // 64

__global__ void __launch_bounds__(256)
k_gemm1_count(const float* __restrict__ A,
              const float* __restrict__ B0, const float* __restrict__ B1,
              float* __restrict__ Co0, float* __restrict__ Co1,
              const int* __restrict__ ei0, const int* __restrict__ ei1,
              const float* __restrict__ as0, const float* __restrict__ as1,
              const float* __restrict__ ad0, const float* __restrict__ ad1,
              float* __restrict__ att) {
    int bid = blockIdx.x;
    int t = threadIdx.x;

    if (bid >= G1_GEMM_BLOCKS) {
        int cid = bid - G1_GEMM_BLOCKS;
        int idx = cid * 256 + t;
        int4 d0 = ((const int4*)(ei0 + EE))[idx];
        int4 d1 = ((const int4*)(ei1 + EE))[idx];
        atomicAdd(&g_cnt[0][d0.x], 1); atomicAdd(&g_cnt[0][d0.y], 1);
        atomicAdd(&g_cnt[0][d0.z], 1); atomicAdd(&g_cnt[0][d0.w], 1);
        atomicAdd(&g_cnt[1][d1.x], 1); atomicAdd(&g_cnt[1][d1.y], 1);
        atomicAdd(&g_cnt[1][d1.z], 1); atomicAdd(&g_cnt[1][d1.w], 1);
        return;
    }

    constexpr int K = 256, Nc = W1O;
    __shared__ float4 sh[768];
    float*  As  = (float*)sh;
    float4* As4 = sh;                            // row stride 32
    float4* Bs4 = sh + 512;                      // [16][16]

    int rel = bid >> 6;
    int r   = bid & 63;
    int bn  = (r & 7) * 64;
    int bm  = (r >> 3) * 128;
    const float* B = rel ? B1 : B0;
    float*       C = rel ? Co1 : Co0;

    int tx = t & 15, ty = t >> 4;
    int am = t >> 2, ak = (t & 3) * 4;

    float4 acc[8];
    #pragma unroll
    for (int i = 0; i < 8; i++) acc[i] = make_float4(0.f, 0.f, 0.f, 0.f);

    float4 a_reg0 = *(const float4*)(A + (size_t)(bm + am) * K + ak);
    float4 a_reg1 = *(const float4*)(A + (size_t)(bm + am + 64) * K + ak);
    float4 b_reg  = *(const float4*)(B + (size_t)(t >> 4) * Nc + bn + (t & 15) * 4);

    for (int k0 = 0; k0 < K; k0 += 16) {
        As[(ak + 0) * 128 + am] = a_reg0.x;
        As[(ak + 1) * 128 + am] = a_reg0.y;
        As[(ak + 2) * 128 + am] = a_reg0.z;
        As[(ak + 3) * 128 + am] = a_reg0.w;
        As[(ak + 0) * 128 + am + 64] = a_reg1.x;
        As[(ak + 1) * 128 + am + 64] = a_reg1.y;
        As[(ak + 2) * 128 + am + 64] = a_reg1.z;
        As[(ak + 3) * 128 + am + 64] = a_reg1.w;
        Bs4[(t >> 4) * 16 + (t & 15)] = b_reg;
        __syncthreads();

        if (k0 + 16 < K) {
            a_reg0 = *(const float4*)(A + (size_t)(bm + am) * K + k0 + 16 + ak);
            a_reg1 = *(const float4*)(A + (size_t)(bm + am + 64) * K + k0 + 16 + ak);
            b_reg  = *(const float4*)(B + (size_t)(k0 + 16 + (t >> 4)) * Nc + bn + (t & 15) * 4);
        }

        #pragma unroll
        for (int k = 0; k < 16; k++) {
            float4 a0 = As4[k * 32 + ty * 2];
            float4 a1 = As4[k * 32 + ty * 2 + 1];
            float4 b  = Bs4[k * 16 + tx];
            float ar[8] = {a0.x, a0.y, a0.z, a0.w, a1.x, a1.y, a1.z, a1.w};
            #pragma unroll
            for (int i = 0; i < 8; i++) {
                acc[i].x = fmaf(ar[i], b.x, acc[i].x);
                acc[i].y = fmaf(ar[i], b.y, acc[i].y);
                acc[i].z = fmaf(ar[i], b.z, acc[i].z);
                acc[i].w = fmaf(ar[i], b.w, acc[i].w);
            }
        }
        __syncthreads();
    }
    #pragma unroll
    for (int i = 0; i < 8; i++)
        *(float4*)(C + (size_t)(bm + ty * 8 + i) * Nc + bn + tx * 4) = acc[i];

    // ---- fused attn1 logit partials ----
    const float* asrc = rel ? as1 : as0;
    const float* adst = rel ? ad1 : ad0;
    int h   = bn >> 8;                       // head (C1=256)
    int cin = (bn & 255) + tx * 4;
    float4 avs = *(const float4*)(asrc + h * C1 + cin);
    float4 avd = *(const float4*)(adst + h * C1 + cin);
    float* alsb = att + (rel * 2 + 0) * (NN * 2);
    float* aldb = att + (rel * 2 + 1) * (NN * 2);
    #pragma unroll
    for (int i = 0; i < 8; i++) {
        float ps = acc[i].x * avs.x + acc[i].y * avs.y + acc[i].z * avs.z + acc[i].w * avs.w;
        float pd = acc[i].x * avd.x + acc[i].y * avd.y + acc[i].z * avd.z + acc[i].w * avd.w;
        #pragma unroll
        for (int o = 8; o; o >>= 1) {
            ps += __shfl_xor_sync(0xffffffffu, ps, o);
            pd += __shfl_xor_sync(0xffffffffu, pd, o);
        }
        if (tx == 0) {
            int row = bm + ty * 8 + i;
            atomicAdd(&alsb[row * 2 + h], ps);
            atomicAdd(&aldb[row * 2 + h], pd);
        }
    }
}

// =======================================================================
// scan (adds self loop)
// =======================================================================
__global__ void k_scan() {
    int r = blockIdx.x;
    int t = threadIdx.x;
    __shared__ int sh[NN];
    int mine = g_cnt[r][t] + 1;
    sh[t] = mine;
    __syncthreads();
    #pragma unroll
    for (int d = 1; d < NN; d <<= 1) {
        int v = (t >= d) ? sh[t - d] : 0;
        __syncthreads();
        sh[t] += v;
        __syncthreads();
    }
    g_off[r][t + 1] = sh[t];
    if (t == 0) g_off[r][0] = 0;
    g_cur[r][t] = sh[t] - mine;
}

// =======================================================================
// CSR fill (4 edges/thread)
// =======================================================================
constexpr int FILL_BLOCKS = E2 / 4 / 256;     // 65

__global__ void __launch_bounds__(256)
k_fill(const int* __restrict__ ei0, const int* __restrict__ ei1) {
    int bid = blockIdx.x;
    int t = threadIdx.x;
    int base = bid * 1024 + t * 4;
    if (base < EE) {
        int idx = bid * 256 + t;
        int4 s0 = ((const int4*)ei0)[idx];
        int4 d0 = ((const int4*)(ei0 + EE))[idx];
        int4 s1 = ((const int4*)ei1)[idx];
        int4 d1 = ((const int4*)(ei1 + EE))[idx];
        int p;
        p = atomicAdd(&g_cur[0][d0.x], 1); g_srcs[0][p] = s0.x;
        p = atomicAdd(&g_cur[0][d0.y], 1); g_srcs[0][p] = s0.y;
        p = atomicAdd(&g_cur[0][d0.z], 1); g_srcs[0][p] = s0.z;
        p = atomicAdd(&g_cur[0][d0.w], 1); g_srcs[0][p] = s0.w;
        p = atomicAdd(&g_cur[1][d1.x], 1); g_srcs[1][p] = s1.x;
        p = atomicAdd(&g_cur[1][d1.y], 1); g_srcs[1][p] = s1.y;
        p = atomicAdd(&g_cur[1][d1.z], 1); g_srcs[1][p] = s1.z;
        p = atomicAdd(&g_cur[1][d1.w], 1); g_srcs[1][p] = s1.w;
    } else {
        #pragma unroll
        for (int u = 0; u < 4; u++) {
            int n = base + u - EE;
            int p0 = atomicAdd(&g_cur[0][n], 1); g_srcs[0][p0] = n;
            int p1 = atomicAdd(&g_cur[1][n], 1); g_srcs[1][p1] = n;
        }
    }
}

// =======================================================================
// gemm2 + fused attn2 logit epilogue
// =======================================================================
__global__ void __launch_bounds__(128)
k_gemm2(const float* __restrict__ A,
        const float* __restrict__ B0, const float* __restrict__ B1,
        float* __restrict__ Co0, float* __restrict__ Co1,
        const float* __restrict__ as0, const float* __restrict__ as1,
        const float* __restrict__ ad0, const float* __restrict__ ad1,
        float* __restrict__ att) {
    constexpr int K = 512, Nc = W2O;
    __shared__ float4 sh[384];
    float*  As  = (float*)sh;
    float4* As4 = sh;                            // row stride 16
    float4* Bs4 = sh + 256;                      // [16][8]

    int bid = blockIdx.x;
    int rel = bid >> 6;
    int r   = bid & 63;
    int bn  = (r & 3) * 32;
    int bm  = (r >> 2) * 64;
    const float* B = rel ? B1 : B0;
    float*       C = rel ? Co1 : Co0;

    int t = threadIdx.x;
    int tx = t & 7, ty = t >> 3;
    int am = t >> 2, ak = (t & 3) * 4;

    float4 acc[4];
    #pragma unroll
    for (int i = 0; i < 4; i++) acc[i] = make_float4(0.f, 0.f, 0.f, 0.f);

    float4 a_reg0 = *(const float4*)(A + (size_t)(bm + am) * K + ak);
    float4 a_reg1 = *(const float4*)(A + (size_t)(bm + am + 32) * K + ak);
    float4 b_reg  = *(const float4*)(B + (size_t)(t >> 3) * Nc + bn + (t & 7) * 4);

    for (int k0 = 0; k0 < K; k0 += 16) {
        As[(ak + 0) * 64 + am] = a_reg0.x;
        As[(ak + 1) * 64 + am] = a_reg0.y;
        As[(ak + 2) * 64 + am] = a_reg0.z;
        As[(ak + 3) * 64 + am] = a_reg0.w;
        As[(ak + 0) * 64 + am + 32] = a_reg1.x;
        As[(ak + 1) * 64 + am + 32] = a_reg1.y;
        As[(ak + 2) * 64 + am + 32] = a_reg1.z;
        As[(ak + 3) * 64 + am + 32] = a_reg1.w;
        Bs4[(t >> 3) * 8 + (t & 7)] = b_reg;
        __syncthreads();

        if (k0 + 16 < K) {
            a_reg0 = *(const float4*)(A + (size_t)(bm + am) * K + k0 + 16 + ak);
            a_reg1 = *(const float4*)(A + (size_t)(bm + am + 32) * K + k0 + 16 + ak);
            b_reg  = *(const float4*)(B + (size_t)(k0 + 16 + (t >> 3)) * Nc + bn + (t & 7) * 4);
        }

        #pragma unroll
        for (int k = 0; k < 16; k++) {
            float4 a = As4[k * 16 + ty];
            float4 b = Bs4[k * 8 + tx];
            float ar[4] = {a.x, a.y, a.z, a.w};
            #pragma unroll
            for (int i = 0; i < 4; i++) {
                acc[i].x = fmaf(ar[i], b.x, acc[i].x);
                acc[i].y = fmaf(ar[i], b.y, acc[i].y);
                acc[i].z = fmaf(ar[i], b.z, acc[i].z);
                acc[i].w = fmaf(ar[i], b.w, acc[i].w);
            }
        }
        __syncthreads();
    }
    #pragma unroll
    for (int i = 0; i < 4; i++)
        *(float4*)(C + (size_t)(bm + ty * 4 + i) * Nc + bn + tx * 4) = acc[i];

    // ---- fused attn2 logit partials ----
    const float* asrc = rel ? as1 : as0;
    const float* adst = rel ? ad1 : ad0;
    int h   = bn >> 6;                       // head (C2=64)
    int cin = (bn & 63) + tx * 4;
    float4 avs = *(const float4*)(asrc + h * C2 + cin);
    float4 avd = *(const float4*)(adst + h * C2 + cin);
    float* alsb = att + (rel * 2 + 0) * (NN * 2);
    float* aldb = att + (rel * 2 + 1) * (NN * 2);
    #pragma unroll
    for (int i = 0; i < 4; i++) {
        float ps = acc[i].x * avs.x + acc[i].y * avs.y + acc[i].z * avs.z + acc[i].w * avs.w;
        float pd = acc[i].x * avd.x + acc[i].y * avd.y + acc[i].z * avd.z + acc[i].w * avd.w;
        #pragma unroll
        for (int o = 4; o; o >>= 1) {
            ps += __shfl_xor_sync(0xffffffffu, ps, o);
            pd += __shfl_xor_sync(0xffffffffu, pd, o);
        }
        if (tx == 0) {
            int row = bm + ty * 4 + i;
            atomicAdd(&alsb[row * 2 + h], ps);
            atomicAdd(&aldb[row * 2 + h], pd);
        }
    }
}

// =======================================================================
// WARP-per-dst softmax+gather (both relations). No __syncthreads on the
// hot path; e-values broadcast by shuffle; rows read as coalesced LDG.128.
// NQ = WOUT/128 accumulators of float4 per lane.
// LAYER==1: h1out = relu(sum + biases). LAYER==2: sout = (sum+biases)·wlin.
// =======================================================================
template <int WOUT, int C, int LAYER>
__global__ void __launch_bounds__(256)
k_aggw(const float* __restrict__ xpA, const float* __restrict__ xpB,
       const float* __restrict__ att,
       const int* __restrict__ off, const int* __restrict__ srcs,
       const float* __restrict__ b0, const float* __restrict__ b1,
       float* __restrict__ h1out, const float* __restrict__ wlin,
       float* __restrict__ sout) {
    constexpr int NQ = WOUT / 128;
    int wid  = threadIdx.x >> 5;
    int lane = threadIdx.x & 31;
    int dst  = blockIdx.x * 8 + wid;

    // head predicate per quarter (compile-time NQ, lane-uniform within quarter
    // only for WOUT=512; lane-dependent for WOUT=128)
    bool hd[NQ];
    #pragma unroll
    for (int q = 0; q < NQ; q++) hd[q] = (q * 128 + lane * 4) >= C;

    float4 tot[NQ];
    #pragma unroll
    for (int q = 0; q < NQ; q++) tot[q] = make_float4(0.f, 0.f, 0.f, 0.f);

    #pragma unroll
    for (int r = 0; r < 2; r++) {
        const float* xp    = r ? xpB : xpA;
        const float* alsr  = att + (r * 2 + 0) * (NN * 2);
        const float* aldr  = att + (r * 2 + 1) * (NN * 2);
        const int*   offr  = off + (size_t)r * (NN + 1);
        const int*   srcsr = srcs + (size_t)r * E2;

        int o0 = offr[dst], o1 = offr[dst + 1];
        int range = o1 - o0;
        float ad0 = aldr[dst * 2 + 0], ad1 = aldr[dst * 2 + 1];

        // pass 1: per-head max of leaky-relu logits (warp-strided)
        float mx0 = -1e30f, mx1 = -1e30f;
        for (int i = lane; i < range; i += 32) {
            int s = srcsr[o0 + i];
            float l0 = alsr[s * 2 + 0] + ad0; l0 = l0 > 0.f ? l0 : 0.2f * l0;
            float l1 = alsr[s * 2 + 1] + ad1; l1 = l1 > 0.f ? l1 : 0.2f * l1;
            mx0 = fmaxf(mx0, l0);
            mx1 = fmaxf(mx1, l1);
        }
        #pragma unroll
        for (int o = 16; o; o >>= 1) {
            mx0 = fmaxf(mx0, __shfl_xor_sync(0xffffffffu, mx0, o));
            mx1 = fmaxf(mx1, __shfl_xor_sync(0xffffffffu, mx1, o));
        }

        float4 a4[NQ];
        #pragma unroll
        for (int q = 0; q < NQ; q++) a4[q] = make_float4(0.f, 0.f, 0.f, 0.f);
        float sum0 = 0.f, sum1 = 0.f;

        for (int base = 0; base < range; base += 32) {
            int cnt = min(32, range - base);
            int   sv = 0;
            float e0 = 0.f, e1 = 0.f;
            if (lane < cnt) {
                sv = srcsr[o0 + base + lane];
                float l0 = alsr[sv * 2 + 0] + ad0; l0 = l0 > 0.f ? l0 : 0.2f * l0;
                float l1 = alsr[sv * 2 + 1] + ad1; l1 = l1 > 0.f ? l1 : 0.2f * l1;
                e0 = expf(l0 - mx0);
                e1 = expf(l1 - mx1);
                sum0 += e0;
                sum1 += e1;
            }
            #pragma unroll 4
            for (int j = 0; j < cnt; j++) {
                int   sj  = __shfl_sync(0xffffffffu, sv, j);
                float ej0 = __shfl_sync(0xffffffffu, e0, j);
                float ej1 = __shfl_sync(0xffffffffu, e1, j);
                const float4* row = (const float4*)(xp + (size_t)sj * WOUT);
                #pragma unroll
                for (int q = 0; q < NQ; q++) {
                    float  e = hd[q] ? ej1 : ej0;
                    float4 v = row[q * 32 + lane];
                    a4[q].x = fmaf(e, v.x, a4[q].x);
                    a4[q].y = fmaf(e, v.y, a4[q].y);
                    a4[q].z = fmaf(e, v.z, a4[q].z);
                    a4[q].w = fmaf(e, v.w, a4[q].w);
                }
            }
        }
        #pragma unroll
        for (int o = 16; o; o >>= 1) {
            sum0 += __shfl_xor_sync(0xffffffffu, sum0, o);
            sum1 += __shfl_xor_sync(0xffffffffu, sum1, o);
        }
        float inv0 = 1.f / (sum0 + 1e-16f);
        float inv1 = 1.f / (sum1 + 1e-16f);
        #pragma unroll
        for (int q = 0; q < NQ; q++) {
            float inv = hd[q] ? inv1 : inv0;
            tot[q].x = fmaf(a4[q].x, inv, tot[q].x);
            tot[q].y = fmaf(a4[q].y, inv, tot[q].y);
            tot[q].z = fmaf(a4[q].z, inv, tot[q].z);
            tot[q].w = fmaf(a4[q].w, inv, tot[q].w);
        }
    }

    if (LAYER == 1) {
        #pragma unroll
        for (int q = 0; q < NQ; q++) {
            float4 bv0 = ((const float4*)b0)[q * 32 + lane];
            float4 bv1 = ((const float4*)b1)[q * 32 + lane];
            float4 v;
            v.x = tot[q].x + bv0.x + bv1.x; v.x = v.x > 0.f ? v.x : 0.f;
            v.y = tot[q].y + bv0.y + bv1.y; v.y = v.y > 0.f ? v.y : 0.f;
            v.z = tot[q].z + bv0.z + bv1.z; v.z = v.z > 0.f ? v.z : 0.f;
            v.w = tot[q].w + bv0.w + bv1.w; v.w = v.w > 0.f ? v.w : 0.f;
            ((float4*)(h1out + (size_t)dst * WOUT))[q * 32 + lane] = v;
        }
    } else {
        float4 bv0 = ((const float4*)b0)[lane];
        float4 bv1 = ((const float4*)b1)[lane];
        float4 wl  = ((const float4*)wlin)[lane];
        float p = (tot[0].x + bv0.x + bv1.x) * wl.x
                + (tot[0].y + bv0.y + bv1.y) * wl.y
                + (tot[0].z + bv0.z + bv1.z) * wl.z
                + (tot[0].w + bv0.w + bv1.w) * wl.w;
        #pragma unroll
        for (int o = 16; o; o >>= 1) p += __shfl_xor_sync(0xffffffffu, p, o);
        if (lane == 0) sout[dst] = p;
    }
}

// ---------------- pairwise output: out[i*N+j] = s[i]+s[j]+b ----------------
__global__ void k_pair(float* __restrict__ out, const float* __restrict__ blin) {
    int idx = blockIdx.x * blockDim.x + threadIdx.x;
    float b = blin[0];
    int i = idx >> 8;
    int j4 = (idx & 255) << 2;
    float si = g_s[i] + b;
    float4 v;
    v.x = si + g_s[j4 + 0];
    v.y = si + g_s[j4 + 1];
    v.z = si + g_s[j4 + 2];
    v.w = si + g_s[j4 + 3];
    ((float4*)out)[idx] = v;
}

// ---------------- launch ----------------
extern "C" void kernel_launch(void* const* d_in, const int* in_sizes, int n_in,
                              void* d_out, int out_size) {
    const float* x    = (const float*)d_in[0];
    const int*   ei0  = (const int*)d_in[1];
    const int*   ei1  = (const int*)d_in[2];
    const float* W1[2]  = {(const float*)d_in[3],  (const float*)d_in[7]};
    const float* as1[2] = {(const float*)d_in[4],  (const float*)d_in[8]};
    const float* ad1[2] = {(const float*)d_in[5],  (const float*)d_in[9]};
    const float* b1[2]  = {(const float*)d_in[6],  (const float*)d_in[10]};
    const float* W2[2]  = {(const float*)d_in[11], (const float*)d_in[15]};
    const float* as2[2] = {(const float*)d_in[12], (const float*)d_in[16]};
    const float* ad2[2] = {(const float*)d_in[13], (const float*)d_in[17]};
    const float* b2[2]  = {(const float*)d_in[14], (const float*)d_in[18]};
    const float* wlin = (const float*)d_in[19];
    const float* blin = (const float*)d_in[20];
    float* out = (float*)d_out;

    float *xp, *h1, *attp, *sp;
    int *cntp, *offp, *srcsp;
    cudaGetSymbolAddress((void**)&xp,    g_xp);
    cudaGetSymbolAddress((void**)&h1,    g_h1);
    cudaGetSymbolAddress((void**)&attp,  g_att);
    cudaGetSymbolAddress((void**)&cntp,  g_cnt);
    cudaGetSymbolAddress((void**)&offp,  g_off);
    cudaGetSymbolAddress((void**)&srcsp, g_srcs);
    cudaGetSymbolAddress((void**)&sp,    g_s);

    float* xp0 = xp;
    float* xp1 = xp + (size_t)NN * W1O;

    cudaMemsetAsync(cntp, 0, 2 * NN * sizeof(int));
    cudaMemsetAsync(attp, 0, 2 * 2 * NN * 2 * sizeof(float));

    // gemm1 (+attn1 epilogue) + edge count
    k_gemm1_count<<<G1_GEMM_BLOCKS + G1_COUNT_BLOCKS, 256>>>(
        x, W1[0], W1[1], xp0, xp1, ei0, ei1,
        as1[0], as1[1], ad1[0], ad1[1], attp);

    k_scan<<<2, 1024>>>();
    k_fill<<<FILL_BLOCKS, 256>>>(ei0, ei1);

    // layer-1 aggregation (warp per dst, +bias+relu fused)
    k_aggw<W1O, C1, 1><<<NN / 8, 256>>>(
        xp0, xp1, attp, offp, srcsp, b1[0], b1[1], h1, nullptr, nullptr);

    cudaMemsetAsync(attp, 0, 2 * 2 * NN * 2 * sizeof(float));

    // gemm2 (+attn2 epilogue)
    k_gemm2<<<128, 128>>>(h1, W2[0], W2[1], xp0, xp1,
                          as2[0], as2[1], ad2[0], ad2[1], attp);

    // layer-2 aggregation (warp per dst, +bias+w_lin fused -> s)
    k_aggw<W2O, C2, 2><<<NN / 8, 256>>>(
        xp0, xp1, attp, offp, srcsp, b2[0], b2[1], nullptr, wlin, sp);

    k_pair<<<NN * NN / 4 / 256, 256>>>(out, blin);
}

// round 7
// speedup vs baseline: 1.4321x; 1.4321x over previous
#include <cuda_runtime.h>
#include <cuda_fp16.h>

#define DEV_INLINE __device__ __forceinline__

constexpr int NN   = 1024;
constexpr int EE   = 65536;
constexpr int E2   = EE + NN;      // edges + self loops
constexpr int W1O  = 512;          // H*256
constexpr int C1   = 256;
constexpr int W2O  = 128;          // H*64
constexpr int C2   = 64;

// ---------------- scratch (device globals) -------------
__device__ __half g_xph[2][NN * W1O];   // layer-1 projected features (fp16 gather copy)
__device__ float  g_xp[2][NN * W2O];    // layer-2 projected features (fp32)
__device__ float  g_h1[NN * W1O];
__device__ float  g_att[2 * 2 * NN * 2];   // [rel][als/ald][node*2+head]
__device__ int    g_cnt[2][NN];
__device__ int    g_off[2][NN + 1];
__device__ int    g_cur[2][NN];
__device__ int    g_srcs[2][E2];
__device__ float  g_s[NN];

// =======================================================================
// FUSED launch: gemm1 (both relations, fp16 output) + attn1 logits
//               (atomic epilogue) + edge counting
// =======================================================================
constexpr int G1_GEMM_BLOCKS  = (W1O / 64) * (NN / 128) * 2;   // 128
constexpr int G1_COUNT_BLOCKS = EE / 4 / 256;                  // 64

__global__ void __launch_bounds__(256)
k_gemm1_count(const float* __restrict__ A,
              const float* __restrict__ B0, const float* __restrict__ B1,
              __half* __restrict__ Ch0, __half* __restrict__ Ch1,
              const int* __restrict__ ei0, const int* __restrict__ ei1,
              const float* __restrict__ as0, const float* __restrict__ as1,
              const float* __restrict__ ad0, const float* __restrict__ ad1,
              float* __restrict__ att) {
    int bid = blockIdx.x;
    int t = threadIdx.x;

    if (bid >= G1_GEMM_BLOCKS) {
        int cid = bid - G1_GEMM_BLOCKS;
        int idx = cid * 256 + t;
        int4 d0 = ((const int4*)(ei0 + EE))[idx];
        int4 d1 = ((const int4*)(ei1 + EE))[idx];
        atomicAdd(&g_cnt[0][d0.x], 1); atomicAdd(&g_cnt[0][d0.y], 1);
        atomicAdd(&g_cnt[0][d0.z], 1); atomicAdd(&g_cnt[0][d0.w], 1);
        atomicAdd(&g_cnt[1][d1.x], 1); atomicAdd(&g_cnt[1][d1.y], 1);
        atomicAdd(&g_cnt[1][d1.z], 1); atomicAdd(&g_cnt[1][d1.w], 1);
        return;
    }

    constexpr int K = 256, Nc = W1O;
    __shared__ float4 sh[768];
    float*  As  = (float*)sh;
    float4* As4 = sh;                            // row stride 32
    float4* Bs4 = sh + 512;                      // [16][16]

    int rel = bid >> 6;
    int r   = bid & 63;
    int bn  = (r & 7) * 64;
    int bm  = (r >> 3) * 128;
    const float* B = rel ? B1 : B0;
    __half*      Ch = rel ? Ch1 : Ch0;

    int tx = t & 15, ty = t >> 4;
    int am = t >> 2, ak = (t & 3) * 4;

    float4 acc[8];
    #pragma unroll
    for (int i = 0; i < 8; i++) acc[i] = make_float4(0.f, 0.f, 0.f, 0.f);

    float4 a_reg0 = *(const float4*)(A + (size_t)(bm + am) * K + ak);
    float4 a_reg1 = *(const float4*)(A + (size_t)(bm + am + 64) * K + ak);
    float4 b_reg  = *(const float4*)(B + (size_t)(t >> 4) * Nc + bn + (t & 15) * 4);

    for (int k0 = 0; k0 < K; k0 += 16) {
        As[(ak + 0) * 128 + am] = a_reg0.x;
        As[(ak + 1) * 128 + am] = a_reg0.y;
        As[(ak + 2) * 128 + am] = a_reg0.z;
        As[(ak + 3) * 128 + am] = a_reg0.w;
        As[(ak + 0) * 128 + am + 64] = a_reg1.x;
        As[(ak + 1) * 128 + am + 64] = a_reg1.y;
        As[(ak + 2) * 128 + am + 64] = a_reg1.z;
        As[(ak + 3) * 128 + am + 64] = a_reg1.w;
        Bs4[(t >> 4) * 16 + (t & 15)] = b_reg;
        __syncthreads();

        if (k0 + 16 < K) {
            a_reg0 = *(const float4*)(A + (size_t)(bm + am) * K + k0 + 16 + ak);
            a_reg1 = *(const float4*)(A + (size_t)(bm + am + 64) * K + k0 + 16 + ak);
            b_reg  = *(const float4*)(B + (size_t)(k0 + 16 + (t >> 4)) * Nc + bn + (t & 15) * 4);
        }

        #pragma unroll
        for (int k = 0; k < 16; k++) {
            float4 a0 = As4[k * 32 + ty * 2];
            float4 a1 = As4[k * 32 + ty * 2 + 1];
            float4 b  = Bs4[k * 16 + tx];
            float ar[8] = {a0.x, a0.y, a0.z, a0.w, a1.x, a1.y, a1.z, a1.w};
            #pragma unroll
            for (int i = 0; i < 8; i++) {
                acc[i].x = fmaf(ar[i], b.x, acc[i].x);
                acc[i].y = fmaf(ar[i], b.y, acc[i].y);
                acc[i].z = fmaf(ar[i], b.z, acc[i].z);
                acc[i].w = fmaf(ar[i], b.w, acc[i].w);
            }
        }
        __syncthreads();
    }
    // fp16 store (gather copy)
    #pragma unroll
    for (int i = 0; i < 8; i++) {
        __half2 h01 = __floats2half2_rn(acc[i].x, acc[i].y);
        __half2 h23 = __floats2half2_rn(acc[i].z, acc[i].w);
        uint2 v;
        v.x = *reinterpret_cast<unsigned*>(&h01);
        v.y = *reinterpret_cast<unsigned*>(&h23);
        ((uint2*)(Ch + (size_t)(bm + ty * 8 + i) * Nc))[(bn >> 2) + tx] = v;
    }

    // ---- fused attn1 logit partials ----
    const float* asrc = rel ? as1 : as0;
    const float* adst = rel ? ad1 : ad0;
    int h   = bn >> 8;                       // head (C1=256)
    int cin = (bn & 255) + tx * 4;
    float4 avs = *(const float4*)(asrc + h * C1 + cin);
    float4 avd = *(const float4*)(adst + h * C1 + cin);
    float* alsb = att + (rel * 2 + 0) * (NN * 2);
    float* aldb = att + (rel * 2 + 1) * (NN * 2);
    #pragma unroll
    for (int i = 0; i < 8; i++) {
        float ps = acc[i].x * avs.x + acc[i].y * avs.y + acc[i].z * avs.z + acc[i].w * avs.w;
        float pd = acc[i].x * avd.x + acc[i].y * avd.y + acc[i].z * avd.z + acc[i].w * avd.w;
        #pragma unroll
        for (int o = 8; o; o >>= 1) {
            ps += __shfl_xor_sync(0xffffffffu, ps, o);
            pd += __shfl_xor_sync(0xffffffffu, pd, o);
        }
        if (tx == 0) {
            int row = bm + ty * 8 + i;
            atomicAdd(&alsb[row * 2 + h], ps);
            atomicAdd(&aldb[row * 2 + h], pd);
        }
    }
}

// =======================================================================
// scan (adds self loop)
// =======================================================================
__global__ void k_scan() {
    int r = blockIdx.x;
    int t = threadIdx.x;
    __shared__ int sh[NN];
    int mine = g_cnt[r][t] + 1;
    sh[t] = mine;
    __syncthreads();
    #pragma unroll
    for (int d = 1; d < NN; d <<= 1) {
        int v = (t >= d) ? sh[t - d] : 0;
        __syncthreads();
        sh[t] += v;
        __syncthreads();
    }
    g_off[r][t + 1] = sh[t];
    if (t == 0) g_off[r][0] = 0;
    g_cur[r][t] = sh[t] - mine;
}

// =======================================================================
// CSR fill (4 edges/thread)
// =======================================================================
constexpr int FILL_BLOCKS = E2 / 4 / 256;     // 65

__global__ void __launch_bounds__(256)
k_fill(const int* __restrict__ ei0, const int* __restrict__ ei1) {
    int bid = blockIdx.x;
    int t = threadIdx.x;
    int base = bid * 1024 + t * 4;
    if (base < EE) {
        int idx = bid * 256 + t;
        int4 s0 = ((const int4*)ei0)[idx];
        int4 d0 = ((const int4*)(ei0 + EE))[idx];
        int4 s1 = ((const int4*)ei1)[idx];
        int4 d1 = ((const int4*)(ei1 + EE))[idx];
        int p;
        p = atomicAdd(&g_cur[0][d0.x], 1); g_srcs[0][p] = s0.x;
        p = atomicAdd(&g_cur[0][d0.y], 1); g_srcs[0][p] = s0.y;
        p = atomicAdd(&g_cur[0][d0.z], 1); g_srcs[0][p] = s0.z;
        p = atomicAdd(&g_cur[0][d0.w], 1); g_srcs[0][p] = s0.w;
        p = atomicAdd(&g_cur[1][d1.x], 1); g_srcs[1][p] = s1.x;
        p = atomicAdd(&g_cur[1][d1.y], 1); g_srcs[1][p] = s1.y;
        p = atomicAdd(&g_cur[1][d1.z], 1); g_srcs[1][p] = s1.z;
        p = atomicAdd(&g_cur[1][d1.w], 1); g_srcs[1][p] = s1.w;
    } else {
        #pragma unroll
        for (int u = 0; u < 4; u++) {
            int n = base + u - EE;
            int p0 = atomicAdd(&g_cur[0][n], 1); g_srcs[0][p0] = n;
            int p1 = atomicAdd(&g_cur[1][n], 1); g_srcs[1][p1] = n;
        }
    }
}

// =======================================================================
// gemm2 + fused attn2 logit epilogue
// =======================================================================
__global__ void __launch_bounds__(128)
k_gemm2(const float* __restrict__ A,
        const float* __restrict__ B0, const float* __restrict__ B1,
        float* __restrict__ Co0, float* __restrict__ Co1,
        const float* __restrict__ as0, const float* __restrict__ as1,
        const float* __restrict__ ad0, const float* __restrict__ ad1,
        float* __restrict__ att) {
    constexpr int K = 512, Nc = W2O;
    __shared__ float4 sh[384];
    float*  As  = (float*)sh;
    float4* As4 = sh;                            // row stride 16
    float4* Bs4 = sh + 256;                      // [16][8]

    int bid = blockIdx.x;
    int rel = bid >> 6;
    int r   = bid & 63;
    int bn  = (r & 3) * 32;
    int bm  = (r >> 2) * 64;
    const float* B = rel ? B1 : B0;
    float*       C = rel ? Co1 : Co0;

    int t = threadIdx.x;
    int tx = t & 7, ty = t >> 3;
    int am = t >> 2, ak = (t & 3) * 4;

    float4 acc[4];
    #pragma unroll
    for (int i = 0; i < 4; i++) acc[i] = make_float4(0.f, 0.f, 0.f, 0.f);

    float4 a_reg0 = *(const float4*)(A + (size_t)(bm + am) * K + ak);
    float4 a_reg1 = *(const float4*)(A + (size_t)(bm + am + 32) * K + ak);
    float4 b_reg  = *(const float4*)(B + (size_t)(t >> 3) * Nc + bn + (t & 7) * 4);

    for (int k0 = 0; k0 < K; k0 += 16) {
        As[(ak + 0) * 64 + am] = a_reg0.x;
        As[(ak + 1) * 64 + am] = a_reg0.y;
        As[(ak + 2) * 64 + am] = a_reg0.z;
        As[(ak + 3) * 64 + am] = a_reg0.w;
        As[(ak + 0) * 64 + am + 32] = a_reg1.x;
        As[(ak + 1) * 64 + am + 32] = a_reg1.y;
        As[(ak + 2) * 64 + am + 32] = a_reg1.z;
        As[(ak + 3) * 64 + am + 32] = a_reg1.w;
        Bs4[(t >> 3) * 8 + (t & 7)] = b_reg;
        __syncthreads();

        if (k0 + 16 < K) {
            a_reg0 = *(const float4*)(A + (size_t)(bm + am) * K + k0 + 16 + ak);
            a_reg1 = *(const float4*)(A + (size_t)(bm + am + 32) * K + k0 + 16 + ak);
            b_reg  = *(const float4*)(B + (size_t)(k0 + 16 + (t >> 3)) * Nc + bn + (t & 7) * 4);
        }

        #pragma unroll
        for (int k = 0; k < 16; k++) {
            float4 a = As4[k * 16 + ty];
            float4 b = Bs4[k * 8 + tx];
            float ar[4] = {a.x, a.y, a.z, a.w};
            #pragma unroll
            for (int i = 0; i < 4; i++) {
                acc[i].x = fmaf(ar[i], b.x, acc[i].x);
                acc[i].y = fmaf(ar[i], b.y, acc[i].y);
                acc[i].z = fmaf(ar[i], b.z, acc[i].z);
                acc[i].w = fmaf(ar[i], b.w, acc[i].w);
            }
        }
        __syncthreads();
    }
    #pragma unroll
    for (int i = 0; i < 4; i++)
        *(float4*)(C + (size_t)(bm + ty * 4 + i) * Nc + bn + tx * 4) = acc[i];

    // ---- fused attn2 logit partials ----
    const float* asrc = rel ? as1 : as0;
    const float* adst = rel ? ad1 : ad0;
    int h   = bn >> 6;                       // head (C2=64)
    int cin = (bn & 63) + tx * 4;
    float4 avs = *(const float4*)(asrc + h * C2 + cin);
    float4 avd = *(const float4*)(adst + h * C2 + cin);
    float* alsb = att + (rel * 2 + 0) * (NN * 2);
    float* aldb = att + (rel * 2 + 1) * (NN * 2);
    #pragma unroll
    for (int i = 0; i < 4; i++) {
        float ps = acc[i].x * avs.x + acc[i].y * avs.y + acc[i].z * avs.z + acc[i].w * avs.w;
        float pd = acc[i].x * avd.x + acc[i].y * avd.y + acc[i].z * avd.z + acc[i].w * avd.w;
        #pragma unroll
        for (int o = 4; o; o >>= 1) {
            ps += __shfl_xor_sync(0xffffffffu, ps, o);
            pd += __shfl_xor_sync(0xffffffffu, pd, o);
        }
        if (tx == 0) {
            int row = bm + ty * 4 + i;
            atomicAdd(&alsb[row * 2 + h], ps);
            atomicAdd(&aldb[row * 2 + h], pd);
        }
    }
}

// =======================================================================
// block-per-dst softmax+gather, single pass (no max subtraction:
// e^a/Σe^a is exactly e^{a-m}/Σe^{a-m}; logits are O(8) so no overflow).
// 128 threads; LAYER 1: fp16 gather, one float4-slice per thread.
// LAYER 2: fp32 scalar per thread + fused bias + w_lin dot.
// =======================================================================
template <int WOUT, int C, int LAYER>
__global__ void __launch_bounds__(128)
k_agg(const void* __restrict__ xpAv, const void* __restrict__ xpBv,
      const float* __restrict__ att,
      const int* __restrict__ off, const int* __restrict__ srcs,
      const float* __restrict__ b0, const float* __restrict__ b1,
      float* __restrict__ h1out, const float* __restrict__ wlin,
      float* __restrict__ sout) {
    constexpr int CH = 512;
    __shared__ int   sh_src[CH];
    __shared__ float sh_e[2][CH];
    __shared__ float red[8];

    int dst = blockIdx.x, t = threadIdx.x;
    int head = (LAYER == 1) ? ((t * 4) >= C ? 1 : 0) : (t >= C ? 1 : 0);

    float4 tot4 = make_float4(0.f, 0.f, 0.f, 0.f);
    float  tot1 = 0.f;

    #pragma unroll
    for (int r = 0; r < 2; r++) {
        const void*  xpv   = r ? xpBv : xpAv;
        const float* alsr  = att + (r * 2 + 0) * (NN * 2);
        const float* aldr  = att + (r * 2 + 1) * (NN * 2);
        const int*   offr  = off + (size_t)r * (NN + 1);
        const int*   srcsr = srcs + (size_t)r * E2;

        int o0 = offr[dst];
        int range = offr[dst + 1] - o0;
        float ad0 = aldr[dst * 2 + 0], ad1 = aldr[dst * 2 + 1];

        float sum0 = 0.f, sum1 = 0.f;
        float4 a4 = make_float4(0.f, 0.f, 0.f, 0.f);
        float  a1 = 0.f;

        for (int base = 0; base < range; base += CH) {
            int nn = min(CH, range - base);
            __syncthreads();
            for (int i = t; i < nn; i += 128) {
                int s = srcsr[o0 + base + i];
                sh_src[i] = s;
                float l0 = alsr[s * 2 + 0] + ad0; l0 = l0 > 0.f ? l0 : 0.2f * l0;
                float l1 = alsr[s * 2 + 1] + ad1; l1 = l1 > 0.f ? l1 : 0.2f * l1;
                float e0 = expf(l0);
                float e1 = expf(l1);
                sh_e[0][i] = e0; sh_e[1][i] = e1;
                sum0 += e0; sum1 += e1;
            }
            __syncthreads();
            const float* eh = sh_e[head];
            if (LAYER == 1) {
                const __half* xph = (const __half*)xpv;
                #pragma unroll 4
                for (int j = 0; j < nn; j++) {
                    int s = sh_src[j];
                    float e = eh[j];
                    uint2 v = ((const uint2*)(xph + (size_t)s * WOUT))[t];
                    __half2 h01 = *reinterpret_cast<__half2*>(&v.x);
                    __half2 h23 = *reinterpret_cast<__half2*>(&v.y);
                    float2 f01 = __half22float2(h01);
                    float2 f23 = __half22float2(h23);
                    a4.x = fmaf(e, f01.x, a4.x);
                    a4.y = fmaf(e, f01.y, a4.y);
                    a4.z = fmaf(e, f23.x, a4.z);
                    a4.w = fmaf(e, f23.y, a4.w);
                }
            } else {
                const float* xpf = (const float*)xpv;
                #pragma unroll 4
                for (int j = 0; j < nn; j++) {
                    int s = sh_src[j];
                    a1 = fmaf(eh[j], xpf[(size_t)s * WOUT + t], a1);
                }
            }
        }
        // combined block reduction of sum0/sum1 (4 warps)
        #pragma unroll
        for (int o = 16; o; o >>= 1) {
            sum0 += __shfl_xor_sync(0xffffffffu, sum0, o);
            sum1 += __shfl_xor_sync(0xffffffffu, sum1, o);
        }
        if ((t & 31) == 0) { red[t >> 5] = sum0; red[4 + (t >> 5)] = sum1; }
        __syncthreads();
        sum0 = red[0] + red[1] + red[2] + red[3];
        sum1 = red[4] + red[5] + red[6] + red[7];
        float inv = head ? 1.f / (sum1 + 1e-16f) : 1.f / (sum0 + 1e-16f);
        if (LAYER == 1) {
            tot4.x = fmaf(a4.x, inv, tot4.x);
            tot4.y = fmaf(a4.y, inv, tot4.y);
            tot4.z = fmaf(a4.z, inv, tot4.z);
            tot4.w = fmaf(a4.w, inv, tot4.w);
        } else {
            tot1 = fmaf(a1, inv, tot1);
        }
        __syncthreads();   // protect red before next relation's write
    }

    if (LAYER == 1) {
        float4 bv0 = ((const float4*)b0)[t];
        float4 bv1 = ((const float4*)b1)[t];
        float4 v;
        v.x = tot4.x + bv0.x + bv1.x; v.x = v.x > 0.f ? v.x : 0.f;
        v.y = tot4.y + bv0.y + bv1.y; v.y = v.y > 0.f ? v.y : 0.f;
        v.z = tot4.z + bv0.z + bv1.z; v.z = v.z > 0.f ? v.z : 0.f;
        v.w = tot4.w + bv0.w + bv1.w; v.w = v.w > 0.f ? v.w : 0.f;
        ((float4*)(h1out + (size_t)dst * WOUT))[t] = v;
    } else {
        float v = tot1 + b0[t] + b1[t];
        float p = v * wlin[t];
        #pragma unroll
        for (int o = 16; o; o >>= 1) p += __shfl_xor_sync(0xffffffffu, p, o);
        if ((t & 31) == 0) red[t >> 5] = p;
        __syncthreads();
        if (t == 0) sout[dst] = red[0] + red[1] + red[2] + red[3];
    }
}

// ---------------- pairwise output: out[i*N+j] = s[i]+s[j]+b ----------------
__global__ void k_pair(float* __restrict__ out, const float* __restrict__ blin) {
    int idx = blockIdx.x * blockDim.x + threadIdx.x;
    float b = blin[0];
    int i = idx >> 8;
    int j4 = (idx & 255) << 2;
    float si = g_s[i] + b;
    float4 v;
    v.x = si + g_s[j4 + 0];
    v.y = si + g_s[j4 + 1];
    v.z = si + g_s[j4 + 2];
    v.w = si + g_s[j4 + 3];
    ((float4*)out)[idx] = v;
}

// ---------------- launch ----------------
extern "C" void kernel_launch(void* const* d_in, const int* in_sizes, int n_in,
                              void* d_out, int out_size) {
    const float* x    = (const float*)d_in[0];
    const int*   ei0  = (const int*)d_in[1];
    const int*   ei1  = (const int*)d_in[2];
    const float* W1[2]  = {(const float*)d_in[3],  (const float*)d_in[7]};
    const float* as1[2] = {(const float*)d_in[4],  (const float*)d_in[8]};
    const float* ad1[2] = {(const float*)d_in[5],  (const float*)d_in[9]};
    const float* b1[2]  = {(const float*)d_in[6],  (const float*)d_in[10]};
    const float* W2[2]  = {(const float*)d_in[11], (const float*)d_in[15]};
    const float* as2[2] = {(const float*)d_in[12], (const float*)d_in[16]};
    const float* ad2[2] = {(const float*)d_in[13], (const float*)d_in[17]};
    const float* b2[2]  = {(const float*)d_in[14], (const float*)d_in[18]};
    const float* wlin = (const float*)d_in[19];
    const float* blin = (const float*)d_in[20];
    float* out = (float*)d_out;

    float *xp, *h1, *attp, *sp;
    __half* xph;
    int *cntp, *offp, *srcsp;
    cudaGetSymbolAddress((void**)&xph,   g_xph);
    cudaGetSymbolAddress((void**)&xp,    g_xp);
    cudaGetSymbolAddress((void**)&h1,    g_h1);
    cudaGetSymbolAddress((void**)&attp,  g_att);
    cudaGetSymbolAddress((void**)&cntp,  g_cnt);
    cudaGetSymbolAddress((void**)&offp,  g_off);
    cudaGetSymbolAddress((void**)&srcsp, g_srcs);
    cudaGetSymbolAddress((void**)&sp,    g_s);

    __half* xph0 = xph;
    __half* xph1 = xph + (size_t)NN * W1O;
    float*  xp0  = xp;
    float*  xp1  = xp + (size_t)NN * W2O;

    cudaMemsetAsync(cntp, 0, 2 * NN * sizeof(int));
    cudaMemsetAsync(attp, 0, 2 * 2 * NN * 2 * sizeof(float));

    // gemm1 (fp16 out, +attn1 epilogue) + edge count
    k_gemm1_count<<<G1_GEMM_BLOCKS + G1_COUNT_BLOCKS, 256>>>(
        x, W1[0], W1[1], xph0, xph1, ei0, ei1,
        as1[0], as1[1], ad1[0], ad1[1], attp);

    k_scan<<<2, 1024>>>();
    k_fill<<<FILL_BLOCKS, 256>>>(ei0, ei1);

    // layer-1 aggregation (block per dst, fp16 gather, +bias+relu fused)
    k_agg<W1O, C1, 1><<<NN, 128>>>(
        xph0, xph1, attp, offp, srcsp, b1[0], b1[1], h1, nullptr, nullptr);

    cudaMemsetAsync(attp, 0, 2 * 2 * NN * 2 * sizeof(float));

    // gemm2 (+attn2 epilogue)
    k_gemm2<<<128, 128>>>(h1, W2[0], W2[1], xp0, xp1,
                          as2[0], as2[1], ad2[0], ad2[1], attp);

    // layer-2 aggregation (block per dst, +bias+w_lin fused -> s)
    k_agg<W2O, C2, 2><<<NN, 128>>>(
        xp0, xp1, attp, offp, srcsp, b2[0], b2[1], nullptr, wlin, sp);

    k_pair<<<NN * NN / 4 / 256, 256>>>(out, blin);
}

// round 8
// speedup vs baseline: 1.4418x; 1.0068x over previous
#include <cuda_runtime.h>
#include <cuda_fp16.h>

#define DEV_INLINE __device__ __forceinline__

constexpr int NN   = 1024;
constexpr int EE   = 65536;
constexpr int E2   = EE + NN;      // edges + self loops
constexpr int W1O  = 512;          // H*256
constexpr int C1   = 256;
constexpr int W2O  = 128;          // H*64
constexpr int C2   = 64;

// ---------------- scratch (device globals) -------------
__device__ __half g_xph[2][NN * W1O];   // layer-1 projected features (fp16)
__device__ float  g_xp[2][NN * W2O];    // layer-2 projected features (fp32)
__device__ float  g_h1a[NN * W1O];      // layer-1 partial (rel 0, normalized)
__device__ float  g_h1b[NN * W1O];      // layer-1 partial (rel 1, normalized)
__device__ float  g_bb[W1O];            // b1_0+b1_1
__device__ float  g_cbias[1];           // sum((b2_0+b2_1)*wlin)
__device__ float  g_att[2 * 2 * NN * 2];
__device__ int    g_cnt4[4][2][NN];     // sharded edge counts
__device__ int    g_cur4[4][2][NN];     // sharded fill cursors
__device__ int    g_off[2][NN + 1];
__device__ int    g_srcs[2][E2];
__device__ float  g_s[NN];

// =======================================================================
// FUSED: gemm1 (both relations, fp16 out) + attn1 logits + sharded count
// =======================================================================
constexpr int G1_GEMM_BLOCKS  = (W1O / 64) * (NN / 128) * 2;   // 128
constexpr int G1_COUNT_BLOCKS = EE / 4 / 256;                  // 64

__global__ void __launch_bounds__(256)
k_gemm1_count(const float* __restrict__ A,
              const float* __restrict__ B0, const float* __restrict__ B1,
              __half* __restrict__ Ch0, __half* __restrict__ Ch1,
              const int* __restrict__ ei0, const int* __restrict__ ei1,
              const float* __restrict__ as0, const float* __restrict__ as1,
              const float* __restrict__ ad0, const float* __restrict__ ad1,
              float* __restrict__ att) {
    int bid = blockIdx.x;
    int t = threadIdx.x;

    if (bid >= G1_GEMM_BLOCKS) {
        int cid = bid - G1_GEMM_BLOCKS;
        int idx = cid * 256 + t;
        int4 d0 = ((const int4*)(ei0 + EE))[idx];
        int4 d1 = ((const int4*)(ei1 + EE))[idx];
        atomicAdd(&g_cnt4[0][0][d0.x], 1); atomicAdd(&g_cnt4[1][0][d0.y], 1);
        atomicAdd(&g_cnt4[2][0][d0.z], 1); atomicAdd(&g_cnt4[3][0][d0.w], 1);
        atomicAdd(&g_cnt4[0][1][d1.x], 1); atomicAdd(&g_cnt4[1][1][d1.y], 1);
        atomicAdd(&g_cnt4[2][1][d1.z], 1); atomicAdd(&g_cnt4[3][1][d1.w], 1);
        return;
    }

    constexpr int K = 256, Nc = W1O;
    __shared__ float4 sh[768];
    float*  As  = (float*)sh;
    float4* As4 = sh;                            // row stride 32
    float4* Bs4 = sh + 512;                      // [16][16]

    int rel = bid >> 6;
    int r   = bid & 63;
    int bn  = (r & 7) * 64;
    int bm  = (r >> 3) * 128;
    const float* B = rel ? B1 : B0;
    __half*      Ch = rel ? Ch1 : Ch0;

    int tx = t & 15, ty = t >> 4;
    int am = t >> 2, ak = (t & 3) * 4;

    float4 acc[8];
    #pragma unroll
    for (int i = 0; i < 8; i++) acc[i] = make_float4(0.f, 0.f, 0.f, 0.f);

    float4 a_reg0 = *(const float4*)(A + (size_t)(bm + am) * K + ak);
    float4 a_reg1 = *(const float4*)(A + (size_t)(bm + am + 64) * K + ak);
    float4 b_reg  = *(const float4*)(B + (size_t)(t >> 4) * Nc + bn + (t & 15) * 4);

    for (int k0 = 0; k0 < K; k0 += 16) {
        As[(ak + 0) * 128 + am] = a_reg0.x;
        As[(ak + 1) * 128 + am] = a_reg0.y;
        As[(ak + 2) * 128 + am] = a_reg0.z;
        As[(ak + 3) * 128 + am] = a_reg0.w;
        As[(ak + 0) * 128 + am + 64] = a_reg1.x;
        As[(ak + 1) * 128 + am + 64] = a_reg1.y;
        As[(ak + 2) * 128 + am + 64] = a_reg1.z;
        As[(ak + 3) * 128 + am + 64] = a_reg1.w;
        Bs4[(t >> 4) * 16 + (t & 15)] = b_reg;
        __syncthreads();

        if (k0 + 16 < K) {
            a_reg0 = *(const float4*)(A + (size_t)(bm + am) * K + k0 + 16 + ak);
            a_reg1 = *(const float4*)(A + (size_t)(bm + am + 64) * K + k0 + 16 + ak);
            b_reg  = *(const float4*)(B + (size_t)(k0 + 16 + (t >> 4)) * Nc + bn + (t & 15) * 4);
        }

        #pragma unroll
        for (int k = 0; k < 16; k++) {
            float4 a0 = As4[k * 32 + ty * 2];
            float4 a1 = As4[k * 32 + ty * 2 + 1];
            float4 b  = Bs4[k * 16 + tx];
            float ar[8] = {a0.x, a0.y, a0.z, a0.w, a1.x, a1.y, a1.z, a1.w};
            #pragma unroll
            for (int i = 0; i < 8; i++) {
                acc[i].x = fmaf(ar[i], b.x, acc[i].x);
                acc[i].y = fmaf(ar[i], b.y, acc[i].y);
                acc[i].z = fmaf(ar[i], b.z, acc[i].z);
                acc[i].w = fmaf(ar[i], b.w, acc[i].w);
            }
        }
        __syncthreads();
    }
    #pragma unroll
    for (int i = 0; i < 8; i++) {
        __half2 h01 = __floats2half2_rn(acc[i].x, acc[i].y);
        __half2 h23 = __floats2half2_rn(acc[i].z, acc[i].w);
        uint2 v;
        v.x = *reinterpret_cast<unsigned*>(&h01);
        v.y = *reinterpret_cast<unsigned*>(&h23);
        ((uint2*)(Ch + (size_t)(bm + ty * 8 + i) * Nc))[(bn >> 2) + tx] = v;
    }

    // fused attn1 logit partials
    const float* asrc = rel ? as1 : as0;
    const float* adst = rel ? ad1 : ad0;
    int h   = bn >> 8;
    int cin = (bn & 255) + tx * 4;
    float4 avs = *(const float4*)(asrc + h * C1 + cin);
    float4 avd = *(const float4*)(adst + h * C1 + cin);
    float* alsb = att + (rel * 2 + 0) * (NN * 2);
    float* aldb = att + (rel * 2 + 1) * (NN * 2);
    #pragma unroll
    for (int i = 0; i < 8; i++) {
        float ps = acc[i].x * avs.x + acc[i].y * avs.y + acc[i].z * avs.z + acc[i].w * avs.w;
        float pd = acc[i].x * avd.x + acc[i].y * avd.y + acc[i].z * avd.z + acc[i].w * avd.w;
        #pragma unroll
        for (int o = 8; o; o >>= 1) {
            ps += __shfl_xor_sync(0xffffffffu, ps, o);
            pd += __shfl_xor_sync(0xffffffffu, pd, o);
        }
        if (tx == 0) {
            int row = bm + ty * 8 + i;
            atomicAdd(&alsb[row * 2 + h], ps);
            atomicAdd(&aldb[row * 2 + h], pd);
        }
    }
}

// =======================================================================
// scan: prefix over 4-shard counts (+self loop); also computes bb, cbias
// =======================================================================
__global__ void k_scan(const float* __restrict__ b1_0, const float* __restrict__ b1_1,
                       const float* __restrict__ b2_0, const float* __restrict__ b2_1,
                       const float* __restrict__ wlin) {
    int r = blockIdx.x;
    int t = threadIdx.x;
    __shared__ int sh[NN];
    __shared__ float fred[4];

    int c0 = g_cnt4[0][r][t] + 1;   // self loop in shard 0
    int c1 = g_cnt4[1][r][t];
    int c2 = g_cnt4[2][r][t];
    int c3 = g_cnt4[3][r][t];
    int mine = c0 + c1 + c2 + c3;
    sh[t] = mine;
    __syncthreads();
    #pragma unroll
    for (int d = 1; d < NN; d <<= 1) {
        int v = (t >= d) ? sh[t - d] : 0;
        __syncthreads();
        sh[t] += v;
        __syncthreads();
    }
    g_off[r][t + 1] = sh[t];
    if (t == 0) g_off[r][0] = 0;
    int base = sh[t] - mine;
    g_cur4[0][r][t] = base;
    g_cur4[1][r][t] = base + c0;
    g_cur4[2][r][t] = base + c0 + c1;
    g_cur4[3][r][t] = base + c0 + c1 + c2;

    // side duties
    if (r == 0) {
        if (t < W1O) g_bb[t] = b1_0[t] + b1_1[t];
    } else {
        float p = 0.f;
        if (t < W2O) p = (b2_0[t] + b2_1[t]) * wlin[t];
        if (t < 128) {
            #pragma unroll
            for (int o = 16; o; o >>= 1) p += __shfl_xor_sync(0xffffffffu, p, o);
            if ((t & 31) == 0) fred[t >> 5] = p;
        }
        __syncthreads();
        if (t == 0) g_cbias[0] = fred[0] + fred[1] + fred[2] + fred[3];
    }
}

// =======================================================================
// CSR fill, sharded cursors (4 edges/thread, one shard per component)
// =======================================================================
constexpr int FILL_BLOCKS = E2 / 4 / 256;     // 65

__global__ void __launch_bounds__(256)
k_fill(const int* __restrict__ ei0, const int* __restrict__ ei1) {
    int bid = blockIdx.x;
    int t = threadIdx.x;
    int base = bid * 1024 + t * 4;
    if (base < EE) {
        int idx = bid * 256 + t;
        int4 s0 = ((const int4*)ei0)[idx];
        int4 d0 = ((const int4*)(ei0 + EE))[idx];
        int4 s1 = ((const int4*)ei1)[idx];
        int4 d1 = ((const int4*)(ei1 + EE))[idx];
        int p;
        p = atomicAdd(&g_cur4[0][0][d0.x], 1); g_srcs[0][p] = s0.x;
        p = atomicAdd(&g_cur4[1][0][d0.y], 1); g_srcs[0][p] = s0.y;
        p = atomicAdd(&g_cur4[2][0][d0.z], 1); g_srcs[0][p] = s0.z;
        p = atomicAdd(&g_cur4[3][0][d0.w], 1); g_srcs[0][p] = s0.w;
        p = atomicAdd(&g_cur4[0][1][d1.x], 1); g_srcs[1][p] = s1.x;
        p = atomicAdd(&g_cur4[1][1][d1.y], 1); g_srcs[1][p] = s1.y;
        p = atomicAdd(&g_cur4[2][1][d1.z], 1); g_srcs[1][p] = s1.z;
        p = atomicAdd(&g_cur4[3][1][d1.w], 1); g_srcs[1][p] = s1.w;
    } else {
        #pragma unroll
        for (int u = 0; u < 4; u++) {
            int n = base + u - EE;
            int p0 = atomicAdd(&g_cur4[0][0][n], 1); g_srcs[0][p0] = n;
            int p1 = atomicAdd(&g_cur4[0][1][n], 1); g_srcs[1][p1] = n;
        }
    }
}

// =======================================================================
// agg1: block per (dst, rel); fp16 gather; writes NORMALIZED partial
// (bias+relu+combine deferred into gemm2's A load)
// =======================================================================
__global__ void __launch_bounds__(128)
k_agg1(const __half* __restrict__ xp0, const __half* __restrict__ xp1,
       const float* __restrict__ att,
       const int* __restrict__ off, const int* __restrict__ srcs,
       float* __restrict__ h1a, float* __restrict__ h1b) {
    constexpr int CH = 512;
    __shared__ int   sh_src[CH];
    __shared__ float sh_e[2][CH];
    __shared__ float red[8];

    int dst = blockIdx.x, rel = blockIdx.y, t = threadIdx.x;
    const __half* xp    = rel ? xp1 : xp0;
    float*        outp  = rel ? h1b : h1a;
    const float*  alsr  = att + (rel * 2 + 0) * (NN * 2);
    const float*  aldr  = att + (rel * 2 + 1) * (NN * 2);
    const int*    offr  = off + (size_t)rel * (NN + 1);
    const int*    srcsr = srcs + (size_t)rel * E2;

    int head = ((t * 4) >= C1) ? 1 : 0;
    int o0 = offr[dst];
    int range = offr[dst + 1] - o0;
    float ad0 = aldr[dst * 2 + 0], ad1 = aldr[dst * 2 + 1];

    float sum0 = 0.f, sum1 = 0.f;
    float4 a4 = make_float4(0.f, 0.f, 0.f, 0.f);

    for (int base = 0; base < range; base += CH) {
        int nn = min(CH, range - base);
        __syncthreads();
        for (int i = t; i < nn; i += 128) {
            int s = srcsr[o0 + base + i];
            sh_src[i] = s;
            float l0 = alsr[s * 2 + 0] + ad0; l0 = l0 > 0.f ? l0 : 0.2f * l0;
            float l1 = alsr[s * 2 + 1] + ad1; l1 = l1 > 0.f ? l1 : 0.2f * l1;
            float e0 = expf(l0);
            float e1 = expf(l1);
            sh_e[0][i] = e0; sh_e[1][i] = e1;
            sum0 += e0; sum1 += e1;
        }
        __syncthreads();
        const float* eh = sh_e[head];
        #pragma unroll 4
        for (int j = 0; j < nn; j++) {
            int s = sh_src[j];
            float e = eh[j];
            uint2 v = ((const uint2*)(xp + (size_t)s * W1O))[t];
            __half2 h01 = *reinterpret_cast<__half2*>(&v.x);
            __half2 h23 = *reinterpret_cast<__half2*>(&v.y);
            float2 f01 = __half22float2(h01);
            float2 f23 = __half22float2(h23);
            a4.x = fmaf(e, f01.x, a4.x);
            a4.y = fmaf(e, f01.y, a4.y);
            a4.z = fmaf(e, f23.x, a4.z);
            a4.w = fmaf(e, f23.y, a4.w);
        }
    }
    #pragma unroll
    for (int o = 16; o; o >>= 1) {
        sum0 += __shfl_xor_sync(0xffffffffu, sum0, o);
        sum1 += __shfl_xor_sync(0xffffffffu, sum1, o);
    }
    if ((t & 31) == 0) { red[t >> 5] = sum0; red[4 + (t >> 5)] = sum1; }
    __syncthreads();
    sum0 = red[0] + red[1] + red[2] + red[3];
    sum1 = red[4] + red[5] + red[6] + red[7];
    float inv = head ? 1.f / (sum1 + 1e-16f) : 1.f / (sum0 + 1e-16f);
    float4 v;
    v.x = a4.x * inv; v.y = a4.y * inv; v.z = a4.z * inv; v.w = a4.w * inv;
    ((float4*)(outp + (size_t)dst * W1O))[t] = v;
}

// =======================================================================
// gemm2: A = relu(h1a + h1b + bb) on the fly; fused attn2 logit epilogue
// =======================================================================
DEV_INLINE float4 ld_h1(const float* __restrict__ h1a, const float* __restrict__ h1b,
                        size_t row, int k) {
    float4 a = *(const float4*)(h1a + row * W1O + k);
    float4 b = *(const float4*)(h1b + row * W1O + k);
    float4 c = *(const float4*)(g_bb + k);
    float4 v;
    v.x = a.x + b.x + c.x; v.x = v.x > 0.f ? v.x : 0.f;
    v.y = a.y + b.y + c.y; v.y = v.y > 0.f ? v.y : 0.f;
    v.z = a.z + b.z + c.z; v.z = v.z > 0.f ? v.z : 0.f;
    v.w = a.w + b.w + c.w; v.w = v.w > 0.f ? v.w : 0.f;
    return v;
}

__global__ void __launch_bounds__(128)
k_gemm2(const float* __restrict__ h1a, const float* __restrict__ h1b,
        const float* __restrict__ B0, const float* __restrict__ B1,
        float* __restrict__ Co0, float* __restrict__ Co1,
        const float* __restrict__ as0, const float* __restrict__ as1,
        const float* __restrict__ ad0, const float* __restrict__ ad1,
        float* __restrict__ att) {
    constexpr int K = 512, Nc = W2O;
    __shared__ float4 sh[384];
    float*  As  = (float*)sh;
    float4* As4 = sh;                            // row stride 16
    float4* Bs4 = sh + 256;                      // [16][8]

    int bid = blockIdx.x;
    int rel = bid >> 6;
    int r   = bid & 63;
    int bn  = (r & 3) * 32;
    int bm  = (r >> 2) * 64;
    const float* B = rel ? B1 : B0;
    float*       C = rel ? Co1 : Co0;

    int t = threadIdx.x;
    int tx = t & 7, ty = t >> 3;
    int am = t >> 2, ak = (t & 3) * 4;

    float4 acc[4];
    #pragma unroll
    for (int i = 0; i < 4; i++) acc[i] = make_float4(0.f, 0.f, 0.f, 0.f);

    float4 a_reg0 = ld_h1(h1a, h1b, (size_t)(bm + am), ak);
    float4 a_reg1 = ld_h1(h1a, h1b, (size_t)(bm + am + 32), ak);
    float4 b_reg  = *(const float4*)(B + (size_t)(t >> 3) * Nc + bn + (t & 7) * 4);

    for (int k0 = 0; k0 < K; k0 += 16) {
        As[(ak + 0) * 64 + am] = a_reg0.x;
        As[(ak + 1) * 64 + am] = a_reg0.y;
        As[(ak + 2) * 64 + am] = a_reg0.z;
        As[(ak + 3) * 64 + am] = a_reg0.w;
        As[(ak + 0) * 64 + am + 32] = a_reg1.x;
        As[(ak + 1) * 64 + am + 32] = a_reg1.y;
        As[(ak + 2) * 64 + am + 32] = a_reg1.z;
        As[(ak + 3) * 64 + am + 32] = a_reg1.w;
        Bs4[(t >> 3) * 8 + (t & 7)] = b_reg;
        __syncthreads();

        if (k0 + 16 < K) {
            a_reg0 = ld_h1(h1a, h1b, (size_t)(bm + am), k0 + 16 + ak);
            a_reg1 = ld_h1(h1a, h1b, (size_t)(bm + am + 32), k0 + 16 + ak);
            b_reg  = *(const float4*)(B + (size_t)(k0 + 16 + (t >> 3)) * Nc + bn + (t & 7) * 4);
        }

        #pragma unroll
        for (int k = 0; k < 16; k++) {
            float4 a = As4[k * 16 + ty];
            float4 b = Bs4[k * 8 + tx];
            float ar[4] = {a.x, a.y, a.z, a.w};
            #pragma unroll
            for (int i = 0; i < 4; i++) {
                acc[i].x = fmaf(ar[i], b.x, acc[i].x);
                acc[i].y = fmaf(ar[i], b.y, acc[i].y);
                acc[i].z = fmaf(ar[i], b.z, acc[i].z);
                acc[i].w = fmaf(ar[i], b.w, acc[i].w);
            }
        }
        __syncthreads();
    }
    #pragma unroll
    for (int i = 0; i < 4; i++)
        *(float4*)(C + (size_t)(bm + ty * 4 + i) * Nc + bn + tx * 4) = acc[i];

    // fused attn2 logit partials
    const float* asrc = rel ? as1 : as0;
    const float* adst = rel ? ad1 : ad0;
    int h   = bn >> 6;
    int cin = (bn & 63) + tx * 4;
    float4 avs = *(const float4*)(asrc + h * C2 + cin);
    float4 avd = *(const float4*)(adst + h * C2 + cin);
    float* alsb = att + (rel * 2 + 0) * (NN * 2);
    float* aldb = att + (rel * 2 + 1) * (NN * 2);
    #pragma unroll
    for (int i = 0; i < 4; i++) {
        float ps = acc[i].x * avs.x + acc[i].y * avs.y + acc[i].z * avs.z + acc[i].w * avs.w;
        float pd = acc[i].x * avd.x + acc[i].y * avd.y + acc[i].z * avd.z + acc[i].w * avd.w;
        #pragma unroll
        for (int o = 4; o; o >>= 1) {
            ps += __shfl_xor_sync(0xffffffffu, ps, o);
            pd += __shfl_xor_sync(0xffffffffu, pd, o);
        }
        if (tx == 0) {
            int row = bm + ty * 4 + i;
            atomicAdd(&alsb[row * 2 + h], ps);
            atomicAdd(&aldb[row * 2 + h], pd);
        }
    }
}

// =======================================================================
// agg2: block per (dst, rel); partial s dot via atomicAdd (s pre-zeroed;
// bias·wlin constant folded into k_pair)
// =======================================================================
__global__ void __launch_bounds__(128)
k_agg2(const float* __restrict__ xp0, const float* __restrict__ xp1,
       const float* __restrict__ att,
       const int* __restrict__ off, const int* __restrict__ srcs,
       const float* __restrict__ wlin, float* __restrict__ sout) {
    constexpr int CH = 512;
    __shared__ int   sh_src[CH];
    __shared__ float sh_e[2][CH];
    __shared__ float red[8];

    int dst = blockIdx.x, rel = blockIdx.y, t = threadIdx.x;
    const float* xp    = rel ? xp1 : xp0;
    const float* alsr  = att + (rel * 2 + 0) * (NN * 2);
    const float* aldr  = att + (rel * 2 + 1) * (NN * 2);
    const int*   offr  = off + (size_t)rel * (NN + 1);
    const int*   srcsr = srcs + (size_t)rel * E2;

    int head = (t >= C2) ? 1 : 0;
    int o0 = offr[dst];
    int range = offr[dst + 1] - o0;
    float ad0 = aldr[dst * 2 + 0], ad1 = aldr[dst * 2 + 1];

    float sum0 = 0.f, sum1 = 0.f;
    float a1 = 0.f;

    for (int base = 0; base < range; base += CH) {
        int nn = min(CH, range - base);
        __syncthreads();
        for (int i = t; i < nn; i += 128) {
            int s = srcsr[o0 + base + i];
            sh_src[i] = s;
            float l0 = alsr[s * 2 + 0] + ad0; l0 = l0 > 0.f ? l0 : 0.2f * l0;
            float l1 = alsr[s * 2 + 1] + ad1; l1 = l1 > 0.f ? l1 : 0.2f * l1;
            float e0 = expf(l0);
            float e1 = expf(l1);
            sh_e[0][i] = e0; sh_e[1][i] = e1;
            sum0 += e0; sum1 += e1;
        }
        __syncthreads();
        const float* eh = sh_e[head];
        #pragma unroll 4
        for (int j = 0; j < nn; j++) {
            int s = sh_src[j];
            a1 = fmaf(eh[j], xp[(size_t)s * W2O + t], a1);
        }
    }
    #pragma unroll
    for (int o = 16; o; o >>= 1) {
        sum0 += __shfl_xor_sync(0xffffffffu, sum0, o);
        sum1 += __shfl_xor_sync(0xffffffffu, sum1, o);
    }
    if ((t & 31) == 0) { red[t >> 5] = sum0; red[4 + (t >> 5)] = sum1; }
    __syncthreads();
    sum0 = red[0] + red[1] + red[2] + red[3];
    sum1 = red[4] + red[5] + red[6] + red[7];
    float inv = head ? 1.f / (sum1 + 1e-16f) : 1.f / (sum0 + 1e-16f);
    float p = a1 * inv * wlin[t];
    #pragma unroll
    for (int o = 16; o; o >>= 1) p += __shfl_xor_sync(0xffffffffu, p, o);
    __syncthreads();
    if ((t & 31) == 0) red[t >> 5] = p;
    __syncthreads();
    if (t == 0) atomicAdd(&sout[dst], red[0] + red[1] + red[2] + red[3]);
}

// ---------------- pairwise output: out[i*N+j] = s[i]+s[j]+2*cbias+b -------
__global__ void k_pair(float* __restrict__ out, const float* __restrict__ blin) {
    int idx = blockIdx.x * blockDim.x + threadIdx.x;
    float b = blin[0] + 2.f * g_cbias[0];
    int i = idx >> 8;
    int j4 = (idx & 255) << 2;
    float si = g_s[i] + b;
    float4 v;
    v.x = si + g_s[j4 + 0];
    v.y = si + g_s[j4 + 1];
    v.z = si + g_s[j4 + 2];
    v.w = si + g_s[j4 + 3];
    ((float4*)out)[idx] = v;
}

// ---------------- launch ----------------
extern "C" void kernel_launch(void* const* d_in, const int* in_sizes, int n_in,
                              void* d_out, int out_size) {
    const float* x    = (const float*)d_in[0];
    const int*   ei0  = (const int*)d_in[1];
    const int*   ei1  = (const int*)d_in[2];
    const float* W1[2]  = {(const float*)d_in[3],  (const float*)d_in[7]};
    const float* as1[2] = {(const float*)d_in[4],  (const float*)d_in[8]};
    const float* ad1[2] = {(const float*)d_in[5],  (const float*)d_in[9]};
    const float* b1[2]  = {(const float*)d_in[6],  (const float*)d_in[10]};
    const float* W2[2]  = {(const float*)d_in[11], (const float*)d_in[15]};
    const float* as2[2] = {(const float*)d_in[12], (const float*)d_in[16]};
    const float* ad2[2] = {(const float*)d_in[13], (const float*)d_in[17]};
    const float* b2[2]  = {(const float*)d_in[14], (const float*)d_in[18]};
    const float* wlin = (const float*)d_in[19];
    const float* blin = (const float*)d_in[20];
    float* out = (float*)d_out;

    float *xp, *h1a, *h1b, *attp, *sp;
    __half* xph;
    int *cnt4p, *offp, *srcsp;
    cudaGetSymbolAddress((void**)&xph,   g_xph);
    cudaGetSymbolAddress((void**)&xp,    g_xp);
    cudaGetSymbolAddress((void**)&h1a,   g_h1a);
    cudaGetSymbolAddress((void**)&h1b,   g_h1b);
    cudaGetSymbolAddress((void**)&attp,  g_att);
    cudaGetSymbolAddress((void**)&cnt4p, g_cnt4);
    cudaGetSymbolAddress((void**)&offp,  g_off);
    cudaGetSymbolAddress((void**)&srcsp, g_srcs);
    cudaGetSymbolAddress((void**)&sp,    g_s);

    __half* xph0 = xph;
    __half* xph1 = xph + (size_t)NN * W1O;
    float*  xp0  = xp;
    float*  xp1  = xp + (size_t)NN * W2O;

    cudaMemsetAsync(cnt4p, 0, 4 * 2 * NN * sizeof(int));
    cudaMemsetAsync(attp, 0, 2 * 2 * NN * 2 * sizeof(float));
    cudaMemsetAsync(sp, 0, NN * sizeof(float));

    // gemm1 (fp16 out, +attn1 epilogue) + sharded edge count
    k_gemm1_count<<<G1_GEMM_BLOCKS + G1_COUNT_BLOCKS, 256>>>(
        x, W1[0], W1[1], xph0, xph1, ei0, ei1,
        as1[0], as1[1], ad1[0], ad1[1], attp);

    k_scan<<<2, 1024>>>(b1[0], b1[1], b2[0], b2[1], wlin);
    k_fill<<<FILL_BLOCKS, 256>>>(ei0, ei1);

    // layer-1 aggregation: block per (dst, rel), normalized partials
    k_agg1<<<dim3(NN, 2), 128>>>(xph0, xph1, attp, offp, srcsp, h1a, h1b);

    cudaMemsetAsync(attp, 0, 2 * 2 * NN * 2 * sizeof(float));

    // gemm2: relu(h1a+h1b+bb) A-load, +attn2 epilogue
    k_gemm2<<<128, 128>>>(h1a, h1b, W2[0], W2[1], xp0, xp1,
                          as2[0], as2[1], ad2[0], ad2[1], attp);

    // layer-2 aggregation: block per (dst, rel) -> s partials
    k_agg2<<<dim3(NN, 2), 128>>>(xp0, xp1, attp, offp, srcsp, wlin, sp);

    k_pair<<<NN * NN / 4 / 256, 256>>>(out, blin);
}